// round 1
// baseline (speedup 1.0000x reference)
#include <cuda_runtime.h>
#include <cstdint>
#include <cstddef>

#define N_NODES 8192
#define F 256

// Scratch (allocation-free rule: device globals)
__device__ float g_Y[(size_t)N_NODES * F];    // X scaled by rsqrt(deg) per row
__device__ float g_rd[N_NODES];               // rsqrt(deg)
__device__ float g_agg[(size_t)N_NODES * F];  // aggregated features

// ---------------------------------------------------------------------------
// Prologue: rd[j] = rsqrt(D[j,j]);  Y[j,:] = X[j,:] * rd[j]
// ---------------------------------------------------------------------------
__global__ void prologue_kernel(const float* __restrict__ D,
                                const float* __restrict__ X) {
    int j = blockIdx.x;
    int c = threadIdx.x;
    __shared__ float s_rd;
    if (c == 0) {
        float d = D[(size_t)j * (N_NODES + 1)];  // diagonal entry
        float r = rsqrtf(d);
        s_rd = r;
        g_rd[j] = r;
    }
    __syncthreads();
    size_t idx = (size_t)j * F + c;
    g_Y[idx] = X[idx] * s_rd;
}

// ---------------------------------------------------------------------------
// Sparse aggregation: one block per node row.
// Scan A[row,:] in 1024-column chunks (float4 per thread), build a 1024-bit
// nonzero mask in shared, then all 256 threads walk the set bits uniformly:
// thread t accumulates channel t of every neighbor's Y row.
// First set bit encountered (ascending order) == first neighbor index.
// ---------------------------------------------------------------------------
__global__ void agg_kernel(const float* __restrict__ A) {
    int row = blockIdx.x;
    int t = threadIdx.x;

    __shared__ uint32_t s_mask[32];

    float acc = 0.0f;
    int firstj = -1;

    const float4* Arow = (const float4*)(A + (size_t)row * N_NODES);

    for (int base = 0; base < N_NODES; base += 1024) {
        if (t < 32) s_mask[t] = 0u;
        __syncthreads();

        float4 v = Arow[(base >> 2) + t];
        uint32_t nib = (v.x > 0.0f ? 1u : 0u) |
                       (v.y > 0.0f ? 2u : 0u) |
                       (v.z > 0.0f ? 4u : 0u) |
                       (v.w > 0.0f ? 8u : 0u);
        if (nib) atomicOr(&s_mask[t >> 3], nib << ((t & 7) * 4));
        __syncthreads();

        #pragma unroll 1
        for (int w = 0; w < 32; ++w) {
            uint32_t m = s_mask[w];
            while (m) {
                int bpos = __ffs(m) - 1;
                m &= (m - 1);
                int j = base + w * 32 + bpos;
                if (firstj < 0) firstj = j;
                acc += g_Y[(size_t)j * F + t];
            }
        }
        __syncthreads();  // protect s_mask before next chunk zeroes it
    }

    // Every row has a self-loop, so firstj >= 0 always.
    acc *= g_rd[firstj];
    g_agg[(size_t)row * F + t] = acc;
}

// ---------------------------------------------------------------------------
// out = leaky_relu(agg @ W^T + b), fp32 tiled GEMM.
// M=8192, N=256, K=256. BM=BN=BK=64, 256 threads, 4x4 microtile.
// Both operands are K-contiguous row-major; shared tiles stored [k][mn]
// (transposed) with pad 68 to keep float4 alignment and avoid conflicts.
// ---------------------------------------------------------------------------
#define BM 64
#define BN 64
#define BK 64
#define SPAD 68

__global__ void gemm_lrelu_kernel(const float* __restrict__ W,
                                  const float* __restrict__ bias,
                                  float* __restrict__ out) {
    __shared__ __align__(16) float sA[BK][SPAD];  // sA[k][m]
    __shared__ __align__(16) float sB[BK][SPAD];  // sB[k][n]

    int tid = threadIdx.x;
    int tx = tid & 15;   // n-group
    int ty = tid >> 4;   // m-group
    int m0 = blockIdx.x * BM;
    int n0 = blockIdx.y * BN;

    float acc[4][4] = {};

    for (int k0 = 0; k0 < F; k0 += BK) {
        // Load 64x64 tiles (1024 float4 each / 256 threads = 4 per thread)
        #pragma unroll
        for (int r = 0; r < 4; ++r) {
            int idx = r * 256 + tid;       // 0..1023
            int mm  = idx >> 4;            // tile row 0..63
            int kk4 = (idx & 15) * 4;      // tile k 0..60 step 4
            float4 va = *(const float4*)&g_agg[(size_t)(m0 + mm) * F + k0 + kk4];
            sA[kk4 + 0][mm] = va.x;
            sA[kk4 + 1][mm] = va.y;
            sA[kk4 + 2][mm] = va.z;
            sA[kk4 + 3][mm] = va.w;
            float4 vb = *(const float4*)&W[(size_t)(n0 + mm) * F + k0 + kk4];
            sB[kk4 + 0][mm] = vb.x;
            sB[kk4 + 1][mm] = vb.y;
            sB[kk4 + 2][mm] = vb.z;
            sB[kk4 + 3][mm] = vb.w;
        }
        __syncthreads();

        #pragma unroll
        for (int k = 0; k < BK; ++k) {
            float4 a4 = *(const float4*)&sA[k][ty * 4];
            float4 b4 = *(const float4*)&sB[k][tx * 4];
            float av[4] = {a4.x, a4.y, a4.z, a4.w};
            float bv[4] = {b4.x, b4.y, b4.z, b4.w};
            #pragma unroll
            for (int i = 0; i < 4; ++i)
                #pragma unroll
                for (int j = 0; j < 4; ++j)
                    acc[i][j] += av[i] * bv[j];
        }
        __syncthreads();
    }

    #pragma unroll
    for (int i = 0; i < 4; ++i) {
        int m = m0 + ty * 4 + i;
        #pragma unroll
        for (int j = 0; j < 4; ++j) {
            int n = n0 + tx * 4 + j;
            float v = acc[i][j] + bias[n];
            out[(size_t)m * F + n] = (v > 0.0f) ? v : 0.01f * v;
        }
    }
}

// ---------------------------------------------------------------------------
// Launch. Inputs (metadata order): D [N*N], X [N*F], A [N*N], W [F*F], b [F]
// ---------------------------------------------------------------------------
extern "C" void kernel_launch(void* const* d_in, const int* in_sizes, int n_in,
                              void* d_out, int out_size) {
    const float* D = (const float*)d_in[0];
    const float* X = (const float*)d_in[1];
    const float* A = (const float*)d_in[2];
    const float* W = (const float*)d_in[3];
    const float* b = (const float*)d_in[4];
    float* out = (float*)d_out;

    prologue_kernel<<<N_NODES, F>>>(D, X);
    agg_kernel<<<N_NODES, 256>>>(A);

    dim3 grid(N_NODES / BM, F / BN);
    gemm_lrelu_kernel<<<grid, 256>>>(W, b, out);
}

// round 2
// speedup vs baseline: 2.3563x; 2.3563x over previous
#include <cuda_runtime.h>
#include <cstdint>
#include <cstddef>

#define N_NODES 8192
#define F 256

// Scratch (allocation-free rule: device globals)
__device__ float g_Y[(size_t)N_NODES * F];    // X scaled by rsqrt(deg) per row
__device__ float g_rd[N_NODES];               // rsqrt(deg)
__device__ float g_agg[(size_t)N_NODES * F];  // aggregated features

// ---------------------------------------------------------------------------
// rd[j] = rsqrt(D[j,j])
// ---------------------------------------------------------------------------
__global__ void rd_kernel(const float* __restrict__ D) {
    int j = blockIdx.x * blockDim.x + threadIdx.x;
    if (j < N_NODES) g_rd[j] = rsqrtf(D[(size_t)j * (N_NODES + 1)]);
}

// ---------------------------------------------------------------------------
// Y[j,:] = X[j,:] * rd[j]  (float4 vectorized; 64 float4 per row)
// ---------------------------------------------------------------------------
__global__ void scale_kernel(const float* __restrict__ X) {
    int idx4 = blockIdx.x * blockDim.x + threadIdx.x;  // float4 index
    int row = idx4 >> 6;                               // F/4 = 64 per row
    float r = g_rd[row];
    float4 v = ((const float4*)X)[idx4];
    v.x *= r; v.y *= r; v.z *= r; v.w *= r;
    ((float4*)g_Y)[idx4] = v;
}

// ---------------------------------------------------------------------------
// Sparse aggregation: one block (256 threads) per node row.
// Phase 1: front-load entire 32KB A row as 8 float4/thread (MLP=8, streaming),
//          compact nonzero column indices into a shared list (shared atomics;
//          ~33 participating threads/row). Track min index for dj0.
// Phase 2: one barrier, then 4-way-unrolled gather of Y rows (MLP=4).
// ---------------------------------------------------------------------------
#define MAX_DEG 1024

__global__ void agg_kernel(const float* __restrict__ A) {
    int row = blockIdx.x;
    int t = threadIdx.x;

    __shared__ int s_idx[MAX_DEG];
    __shared__ int s_cnt;
    __shared__ int s_minj;

    if (t == 0) { s_cnt = 0; s_minj = N_NODES; }
    __syncthreads();

    const float4* Arow = (const float4*)(A + (size_t)row * N_NODES);

    // Front-load the whole row slice: 8 independent streaming loads.
    float4 v[8];
    #pragma unroll
    for (int c = 0; c < 8; ++c)
        v[c] = __ldcs(&Arow[c * 256 + t]);

    #pragma unroll
    for (int c = 0; c < 8; ++c) {
        int col0 = c * 1024 + t * 4;
        uint32_t nib = (v[c].x > 0.0f ? 1u : 0u) |
                       (v[c].y > 0.0f ? 2u : 0u) |
                       (v[c].z > 0.0f ? 4u : 0u) |
                       (v[c].w > 0.0f ? 8u : 0u);
        if (nib) {
            int n = __popc(nib);
            int off = atomicAdd(&s_cnt, n);
            atomicMin(&s_minj, col0 + (__ffs(nib) - 1));
            while (nib) {
                int b = __ffs(nib) - 1;
                nib &= nib - 1;
                if (off < MAX_DEG) s_idx[off] = col0 + b;
                ++off;
            }
        }
    }
    __syncthreads();

    int cnt = s_cnt;
    if (cnt > MAX_DEG) cnt = MAX_DEG;

    // 4-way unrolled gather: independent accumulators expose MLP.
    float a0 = 0.f, a1 = 0.f, a2 = 0.f, a3 = 0.f;
    int i = 0;
    for (; i + 4 <= cnt; i += 4) {
        int j0 = s_idx[i], j1 = s_idx[i + 1], j2 = s_idx[i + 2], j3 = s_idx[i + 3];
        a0 += g_Y[(size_t)j0 * F + t];
        a1 += g_Y[(size_t)j1 * F + t];
        a2 += g_Y[(size_t)j2 * F + t];
        a3 += g_Y[(size_t)j3 * F + t];
    }
    for (; i < cnt; ++i)
        a0 += g_Y[(size_t)s_idx[i] * F + t];

    float acc = (a0 + a1) + (a2 + a3);
    acc *= g_rd[s_minj];
    g_agg[(size_t)row * F + t] = acc;
}

// ---------------------------------------------------------------------------
// out = leaky_relu(agg @ W^T + b), fp32 tiled GEMM.
// M=8192, N=256, K=256. BM=BN=BK=64, 256 threads, 4x4 microtile.
// ---------------------------------------------------------------------------
#define BM 64
#define BN 64
#define BK 64
#define SPAD 68

__global__ void gemm_lrelu_kernel(const float* __restrict__ W,
                                  const float* __restrict__ bias,
                                  float* __restrict__ out) {
    __shared__ __align__(16) float sA[BK][SPAD];  // sA[k][m]
    __shared__ __align__(16) float sB[BK][SPAD];  // sB[k][n]

    int tid = threadIdx.x;
    int tx = tid & 15;   // n-group
    int ty = tid >> 4;   // m-group
    int m0 = blockIdx.x * BM;
    int n0 = blockIdx.y * BN;

    float acc[4][4] = {};

    for (int k0 = 0; k0 < F; k0 += BK) {
        #pragma unroll
        for (int r = 0; r < 4; ++r) {
            int idx = r * 256 + tid;       // 0..1023
            int mm  = idx >> 4;            // tile row 0..63
            int kk4 = (idx & 15) * 4;      // tile k 0..60 step 4
            float4 va = *(const float4*)&g_agg[(size_t)(m0 + mm) * F + k0 + kk4];
            sA[kk4 + 0][mm] = va.x;
            sA[kk4 + 1][mm] = va.y;
            sA[kk4 + 2][mm] = va.z;
            sA[kk4 + 3][mm] = va.w;
            float4 vb = *(const float4*)&W[(size_t)(n0 + mm) * F + k0 + kk4];
            sB[kk4 + 0][mm] = vb.x;
            sB[kk4 + 1][mm] = vb.y;
            sB[kk4 + 2][mm] = vb.z;
            sB[kk4 + 3][mm] = vb.w;
        }
        __syncthreads();

        #pragma unroll
        for (int k = 0; k < BK; ++k) {
            float4 a4 = *(const float4*)&sA[k][ty * 4];
            float4 b4 = *(const float4*)&sB[k][tx * 4];
            float av[4] = {a4.x, a4.y, a4.z, a4.w};
            float bv[4] = {b4.x, b4.y, b4.z, b4.w};
            #pragma unroll
            for (int i = 0; i < 4; ++i)
                #pragma unroll
                for (int j = 0; j < 4; ++j)
                    acc[i][j] += av[i] * bv[j];
        }
        __syncthreads();
    }

    #pragma unroll
    for (int i = 0; i < 4; ++i) {
        int m = m0 + ty * 4 + i;
        #pragma unroll
        for (int j = 0; j < 4; ++j) {
            int n = n0 + tx * 4 + j;
            float v = acc[i][j] + bias[n];
            out[(size_t)m * F + n] = (v > 0.0f) ? v : 0.01f * v;
        }
    }
}

// ---------------------------------------------------------------------------
// Launch. Inputs (metadata order): D [N*N], X [N*F], A [N*N], W [F*F], b [F]
// ---------------------------------------------------------------------------
extern "C" void kernel_launch(void* const* d_in, const int* in_sizes, int n_in,
                              void* d_out, int out_size) {
    const float* D = (const float*)d_in[0];
    const float* X = (const float*)d_in[1];
    const float* A = (const float*)d_in[2];
    const float* W = (const float*)d_in[3];
    const float* b = (const float*)d_in[4];
    float* out = (float*)d_out;

    rd_kernel<<<N_NODES / 256, 256>>>(D);
    scale_kernel<<<(N_NODES * F / 4) / 256, 256>>>(X);
    agg_kernel<<<N_NODES, 256>>>(A);

    dim3 grid(N_NODES / BM, F / BN);
    gemm_lrelu_kernel<<<grid, 256>>>(W, b, out);
}

// round 3
// speedup vs baseline: 2.9909x; 1.2693x over previous
#include <cuda_runtime.h>
#include <cuda_bf16.h>
#include <cstdint>
#include <cstddef>

#define N_NODES 8192
#define F 256

// Scratch (allocation-free rule: device globals)
__device__ float g_rd[N_NODES];                          // rsqrt(deg)
__device__ __nv_bfloat16 g_Ah[(size_t)N_NODES * F];      // agg hi (bf16)
__device__ __nv_bfloat16 g_Al[(size_t)N_NODES * F];      // agg lo (bf16 residual)
__device__ __nv_bfloat16 g_Wh[(size_t)F * F];            // W hi
__device__ __nv_bfloat16 g_Wl[(size_t)F * F];            // W lo

// ---------------------------------------------------------------------------
// rd[j] = rsqrt(D[j,j])
// ---------------------------------------------------------------------------
__global__ void rd_kernel(const float* __restrict__ D) {
    int j = blockIdx.x * blockDim.x + threadIdx.x;
    if (j < N_NODES) g_rd[j] = rsqrtf(D[(size_t)j * (N_NODES + 1)]);
}

// ---------------------------------------------------------------------------
// Split W into bf16 hi + residual lo
// ---------------------------------------------------------------------------
__global__ void wsplit_kernel(const float* __restrict__ W) {
    int i = blockIdx.x * blockDim.x + threadIdx.x;
    float w = W[i];
    __nv_bfloat16 h = __float2bfloat16(w);
    g_Wh[i] = h;
    g_Wl[i] = __float2bfloat16(w - __bfloat162float(h));
}

// ---------------------------------------------------------------------------
// Sparse aggregation, fused with rsqrt scaling and bf16 hi/lo split epilogue.
// One block (256 threads) per node row.
// Phase 1: front-load the 32KB A row (8 float4/thread, MLP=8, streaming),
//          compact nonzero column indices into shared; atomicMin for dj0.
// Phase 2: 4-way unrolled gather: acc += X[j,t] * rd[j]  (rd[j] is a
//          warp-uniform broadcast load).
// ---------------------------------------------------------------------------
#define MAX_DEG 1024

__global__ void agg_kernel(const float* __restrict__ A,
                           const float* __restrict__ X) {
    int row = blockIdx.x;
    int t = threadIdx.x;

    __shared__ int s_idx[MAX_DEG];
    __shared__ int s_cnt;
    __shared__ int s_minj;

    if (t == 0) { s_cnt = 0; s_minj = N_NODES; }
    __syncthreads();

    const float4* Arow = (const float4*)(A + (size_t)row * N_NODES);

    float4 v[8];
    #pragma unroll
    for (int c = 0; c < 8; ++c)
        v[c] = __ldcs(&Arow[c * 256 + t]);

    #pragma unroll
    for (int c = 0; c < 8; ++c) {
        int col0 = c * 1024 + t * 4;
        uint32_t nib = (v[c].x > 0.0f ? 1u : 0u) |
                       (v[c].y > 0.0f ? 2u : 0u) |
                       (v[c].z > 0.0f ? 4u : 0u) |
                       (v[c].w > 0.0f ? 8u : 0u);
        if (nib) {
            int n = __popc(nib);
            int off = atomicAdd(&s_cnt, n);
            atomicMin(&s_minj, col0 + (__ffs(nib) - 1));
            while (nib) {
                int b = __ffs(nib) - 1;
                nib &= nib - 1;
                if (off < MAX_DEG) s_idx[off] = col0 + b;
                ++off;
            }
        }
    }
    __syncthreads();

    int cnt = s_cnt;
    if (cnt > MAX_DEG) cnt = MAX_DEG;

    float a0 = 0.f, a1 = 0.f, a2 = 0.f, a3 = 0.f;
    int i = 0;
    for (; i + 4 <= cnt; i += 4) {
        int j0 = s_idx[i], j1 = s_idx[i + 1], j2 = s_idx[i + 2], j3 = s_idx[i + 3];
        float r0 = g_rd[j0], r1 = g_rd[j1], r2 = g_rd[j2], r3 = g_rd[j3];
        a0 += X[(size_t)j0 * F + t] * r0;
        a1 += X[(size_t)j1 * F + t] * r1;
        a2 += X[(size_t)j2 * F + t] * r2;
        a3 += X[(size_t)j3 * F + t] * r3;
    }
    for (; i < cnt; ++i) {
        int j = s_idx[i];
        a0 += X[(size_t)j * F + t] * g_rd[j];
    }

    float acc = ((a0 + a1) + (a2 + a3)) * g_rd[s_minj];

    // bf16 hi/lo split for the tensor-core GEMM
    __nv_bfloat16 h = __float2bfloat16(acc);
    float lo = acc - __bfloat162float(h);
    size_t oi = (size_t)row * F + t;
    g_Ah[oi] = h;
    g_Al[oi] = __float2bfloat16(lo);
}

// ---------------------------------------------------------------------------
// Tensor-core GEMM: out = leaky_relu(A @ W^T + b) via split bf16:
//   A@W^T ~= Ah@Wh^T + Ah@Wl^T + Al@Wh^T   (fp32 accumulate)
// mma.sync m16n8k16 row.col; both operands K-major in smem; ldmatrix loads.
// Block tile 128x64, BK=32, 256 threads = 8 warps (4x2), warp tile 32x32.
// ---------------------------------------------------------------------------
#define GBM 128
#define GBN 64
#define GBK 32
#define SKP 40   // padded K extent in bf16 (80B rows: 16B-aligned, ldmatrix conflict-free)

__device__ __forceinline__ void ldmA4(uint32_t* r, uint32_t addr) {
    asm volatile("ldmatrix.sync.aligned.m8n8.x4.shared.b16 {%0,%1,%2,%3}, [%4];"
        : "=r"(r[0]), "=r"(r[1]), "=r"(r[2]), "=r"(r[3]) : "r"(addr));
}
__device__ __forceinline__ void ldmB2(uint32_t* r, uint32_t addr) {
    asm volatile("ldmatrix.sync.aligned.m8n8.x2.shared.b16 {%0,%1}, [%2];"
        : "=r"(r[0]), "=r"(r[1]) : "r"(addr));
}
__device__ __forceinline__ void mma16816(float* d, const uint32_t* a, const uint32_t* b) {
    asm volatile("mma.sync.aligned.m16n8k16.row.col.f32.bf16.bf16.f32 "
        "{%0,%1,%2,%3}, {%4,%5,%6,%7}, {%8,%9}, {%0,%1,%2,%3};"
        : "+f"(d[0]), "+f"(d[1]), "+f"(d[2]), "+f"(d[3])
        : "r"(a[0]), "r"(a[1]), "r"(a[2]), "r"(a[3]), "r"(b[0]), "r"(b[1]));
}

__global__ void gemm_bf16_kernel(const float* __restrict__ bias,
                                 float* __restrict__ out) {
    __shared__ __align__(16) __nv_bfloat16 sAh[GBM][SKP];
    __shared__ __align__(16) __nv_bfloat16 sAl[GBM][SKP];
    __shared__ __align__(16) __nv_bfloat16 sWh[GBN][SKP];
    __shared__ __align__(16) __nv_bfloat16 sWl[GBN][SKP];

    int tid = threadIdx.x;
    int warp = tid >> 5;
    int lane = tid & 31;
    int m0 = blockIdx.x * GBM;
    int n0 = blockIdx.y * GBN;
    int wm = warp >> 1;   // 0..3 -> m offset wm*32
    int wn = warp & 1;    // 0..1 -> n offset wn*32

    float acc[2][4][4] = {};

    for (int kt = 0; kt < F / GBK; ++kt) {
        int k0 = kt * GBK;

        // A tiles: 128 rows x 32 bf16 = 512 uint4 per tile -> 2 per thread
        #pragma unroll
        for (int r = 0; r < 2; ++r) {
            int idx = r * 256 + tid;      // 0..511
            int mm  = idx >> 2;           // 0..127
            int c4  = idx & 3;            // uint4 index within 32 bf16
            size_t gi = (size_t)(m0 + mm) * F + k0 + c4 * 8;
            *(uint4*)&sAh[mm][c4 * 8] = *(const uint4*)&g_Ah[gi];
            *(uint4*)&sAl[mm][c4 * 8] = *(const uint4*)&g_Al[gi];
        }
        // W tiles: 64 rows x 32 bf16 = 256 uint4 per tile -> 1 per thread
        {
            int nn = tid >> 2;
            int c4 = tid & 3;
            size_t gi = (size_t)(n0 + nn) * F + k0 + c4 * 8;
            *(uint4*)&sWh[nn][c4 * 8] = *(const uint4*)&g_Wh[gi];
            *(uint4*)&sWl[nn][c4 * 8] = *(const uint4*)&g_Wl[gi];
        }
        __syncthreads();

        #pragma unroll
        for (int kk = 0; kk < GBK; kk += 16) {
            uint32_t ah[2][4], al[2][4];
            #pragma unroll
            for (int mi = 0; mi < 2; ++mi) {
                int rowa = wm * 32 + mi * 16 + (lane & 15);
                int cola = kk + (lane >> 4) * 8;
                ldmA4(ah[mi], (uint32_t)__cvta_generic_to_shared(&sAh[rowa][cola]));
                ldmA4(al[mi], (uint32_t)__cvta_generic_to_shared(&sAl[rowa][cola]));
            }
            uint32_t bh[4][2], bl[4][2];
            #pragma unroll
            for (int ni = 0; ni < 4; ++ni) {
                int rowb = wn * 32 + ni * 8 + (lane & 7);
                int colb = kk + ((lane >> 3) & 1) * 8;
                ldmB2(bh[ni], (uint32_t)__cvta_generic_to_shared(&sWh[rowb][colb]));
                ldmB2(bl[ni], (uint32_t)__cvta_generic_to_shared(&sWl[rowb][colb]));
            }
            #pragma unroll
            for (int mi = 0; mi < 2; ++mi)
                #pragma unroll
                for (int ni = 0; ni < 4; ++ni) {
                    mma16816(acc[mi][ni], ah[mi], bh[ni]);
                    mma16816(acc[mi][ni], ah[mi], bl[ni]);
                    mma16816(acc[mi][ni], al[mi], bh[ni]);
                }
        }
        __syncthreads();
    }

    // Epilogue: bias + leaky_relu, mma C-fragment layout
    #pragma unroll
    for (int mi = 0; mi < 2; ++mi) {
        #pragma unroll
        for (int ni = 0; ni < 4; ++ni) {
            int m = m0 + wm * 32 + mi * 16 + (lane >> 2);
            int n = n0 + wn * 32 + ni * 8 + (lane & 3) * 2;
            float b0 = bias[n], b1 = bias[n + 1];
            float v0 = acc[mi][ni][0] + b0;
            float v1 = acc[mi][ni][1] + b1;
            float v2 = acc[mi][ni][2] + b0;
            float v3 = acc[mi][ni][3] + b1;
            out[(size_t)m * F + n]           = v0 > 0.f ? v0 : 0.01f * v0;
            out[(size_t)m * F + n + 1]       = v1 > 0.f ? v1 : 0.01f * v1;
            out[(size_t)(m + 8) * F + n]     = v2 > 0.f ? v2 : 0.01f * v2;
            out[(size_t)(m + 8) * F + n + 1] = v3 > 0.f ? v3 : 0.01f * v3;
        }
    }
}

// ---------------------------------------------------------------------------
// Launch. Inputs (metadata order): D [N*N], X [N*F], A [N*N], W [F*F], b [F]
// ---------------------------------------------------------------------------
extern "C" void kernel_launch(void* const* d_in, const int* in_sizes, int n_in,
                              void* d_out, int out_size) {
    const float* D = (const float*)d_in[0];
    const float* X = (const float*)d_in[1];
    const float* A = (const float*)d_in[2];
    const float* W = (const float*)d_in[3];
    const float* b = (const float*)d_in[4];
    float* out = (float*)d_out;

    rd_kernel<<<N_NODES / 256, 256>>>(D);
    wsplit_kernel<<<F * F / 256, 256>>>(W);
    agg_kernel<<<N_NODES, 256>>>(A, X);

    dim3 grid(N_NODES / GBM, F / GBN);
    gemm_bf16_kernel<<<grid, 256>>>(b, out);
}

// round 4
// speedup vs baseline: 3.1458x; 1.0518x over previous
#include <cuda_runtime.h>
#include <cuda_bf16.h>
#include <cstdint>
#include <cstddef>

#define N_NODES 8192
#define F 256

// Scratch (allocation-free rule: device globals)
__device__ float g_rd[N_NODES];                          // rsqrt(deg)
__device__ __nv_bfloat16 g_Ah[(size_t)N_NODES * F];      // agg hi (bf16)
__device__ __nv_bfloat16 g_Al[(size_t)N_NODES * F];      // agg lo (bf16 residual)
__device__ __nv_bfloat16 g_Wh[(size_t)F * F];            // W hi
__device__ __nv_bfloat16 g_Wl[(size_t)F * F];            // W lo

// ---------------------------------------------------------------------------
// rd[j] = rsqrt(D[j,j])
// ---------------------------------------------------------------------------
__global__ void rd_kernel(const float* __restrict__ D) {
    int j = blockIdx.x * blockDim.x + threadIdx.x;
    if (j < N_NODES) g_rd[j] = rsqrtf(D[(size_t)j * (N_NODES + 1)]);
}

// ---------------------------------------------------------------------------
// Split W into bf16 hi + residual lo
// ---------------------------------------------------------------------------
__global__ void wsplit_kernel(const float* __restrict__ W) {
    int i = blockIdx.x * blockDim.x + threadIdx.x;
    float w = W[i];
    __nv_bfloat16 h = __float2bfloat16(w);
    g_Wh[i] = h;
    g_Wl[i] = __float2bfloat16(w - __bfloat162float(h));
}

// ---------------------------------------------------------------------------
// Sparse aggregation, fused rsqrt scaling, bf16 hi/lo split epilogue.
// One block (256 threads) per node row.
// ---------------------------------------------------------------------------
#define MAX_DEG 1024

__global__ void agg_kernel(const float* __restrict__ A,
                           const float* __restrict__ X) {
    int row = blockIdx.x;
    int t = threadIdx.x;

    __shared__ int s_idx[MAX_DEG];
    __shared__ int s_cnt;
    __shared__ int s_minj;

    if (t == 0) { s_cnt = 0; s_minj = N_NODES; }
    __syncthreads();

    const float4* Arow = (const float4*)(A + (size_t)row * N_NODES);

    float4 v[8];
    #pragma unroll
    for (int c = 0; c < 8; ++c)
        v[c] = __ldcs(&Arow[c * 256 + t]);

    #pragma unroll
    for (int c = 0; c < 8; ++c) {
        int col0 = c * 1024 + t * 4;
        uint32_t nib = (v[c].x > 0.0f ? 1u : 0u) |
                       (v[c].y > 0.0f ? 2u : 0u) |
                       (v[c].z > 0.0f ? 4u : 0u) |
                       (v[c].w > 0.0f ? 8u : 0u);
        if (nib) {
            int n = __popc(nib);
            int off = atomicAdd(&s_cnt, n);
            atomicMin(&s_minj, col0 + (__ffs(nib) - 1));
            while (nib) {
                int b = __ffs(nib) - 1;
                nib &= nib - 1;
                if (off < MAX_DEG) s_idx[off] = col0 + b;
                ++off;
            }
        }
    }
    __syncthreads();

    int cnt = s_cnt;
    if (cnt > MAX_DEG) cnt = MAX_DEG;

    // 8-way unrolled gather: 8 independent accumulators, batched index loads.
    float a[8] = {0.f, 0.f, 0.f, 0.f, 0.f, 0.f, 0.f, 0.f};
    int i = 0;
    for (; i + 8 <= cnt; i += 8) {
        int j[8];
        #pragma unroll
        for (int q = 0; q < 8; ++q) j[q] = s_idx[i + q];
        float r[8];
        #pragma unroll
        for (int q = 0; q < 8; ++q) r[q] = g_rd[j[q]];
        #pragma unroll
        for (int q = 0; q < 8; ++q)
            a[q] += X[(size_t)j[q] * F + t] * r[q];
    }
    for (; i < cnt; ++i) {
        int j = s_idx[i];
        a[0] += X[(size_t)j * F + t] * g_rd[j];
    }

    float acc = ((a[0] + a[1]) + (a[2] + a[3])) + ((a[4] + a[5]) + (a[6] + a[7]));
    acc *= g_rd[s_minj];

    __nv_bfloat16 h = __float2bfloat16(acc);
    float lo = acc - __bfloat162float(h);
    size_t oi = (size_t)row * F + t;
    g_Ah[oi] = h;
    g_Al[oi] = __float2bfloat16(lo);
}

// ---------------------------------------------------------------------------
// Tensor-core GEMM: out = leaky_relu(A @ W^T + b) via split bf16:
//   A@W^T ~= Ah@Wh^T + Ah@Wl^T + Al@Wh^T   (fp32 accumulate)
// cp.async double-buffered. Block tile 128x64, BK=32, 8 warps, warp 32x32.
// ---------------------------------------------------------------------------
#define GBM 128
#define GBN 64
#define GBK 32
#define SKP 40   // padded K extent in bf16 (80B rows)
#define NKT (F / GBK)

__device__ __forceinline__ void ldmA4(uint32_t* r, uint32_t addr) {
    asm volatile("ldmatrix.sync.aligned.m8n8.x4.shared.b16 {%0,%1,%2,%3}, [%4];"
        : "=r"(r[0]), "=r"(r[1]), "=r"(r[2]), "=r"(r[3]) : "r"(addr));
}
__device__ __forceinline__ void ldmB2(uint32_t* r, uint32_t addr) {
    asm volatile("ldmatrix.sync.aligned.m8n8.x2.shared.b16 {%0,%1}, [%2];"
        : "=r"(r[0]), "=r"(r[1]) : "r"(addr));
}
__device__ __forceinline__ void mma16816(float* d, const uint32_t* a, const uint32_t* b) {
    asm volatile("mma.sync.aligned.m16n8k16.row.col.f32.bf16.bf16.f32 "
        "{%0,%1,%2,%3}, {%4,%5,%6,%7}, {%8,%9}, {%0,%1,%2,%3};"
        : "+f"(d[0]), "+f"(d[1]), "+f"(d[2]), "+f"(d[3])
        : "r"(a[0]), "r"(a[1]), "r"(a[2]), "r"(a[3]), "r"(b[0]), "r"(b[1]));
}
__device__ __forceinline__ void cpasync16(void* smem_dst, const void* gsrc) {
    uint32_t d = (uint32_t)__cvta_generic_to_shared(smem_dst);
    asm volatile("cp.async.cg.shared.global [%0], [%1], 16;" :: "r"(d), "l"(gsrc));
}

__global__ __launch_bounds__(256, 2)
void gemm_bf16_kernel(const float* __restrict__ bias,
                      float* __restrict__ out) {
    __shared__ __align__(16) __nv_bfloat16 sAh[2][GBM][SKP];
    __shared__ __align__(16) __nv_bfloat16 sAl[2][GBM][SKP];
    __shared__ __align__(16) __nv_bfloat16 sWh[2][GBN][SKP];
    __shared__ __align__(16) __nv_bfloat16 sWl[2][GBN][SKP];

    int tid = threadIdx.x;
    int warp = tid >> 5;
    int lane = tid & 31;
    int m0 = blockIdx.x * GBM;
    int n0 = blockIdx.y * GBN;
    int wm = warp >> 1;
    int wn = warp & 1;

    // per-thread load coordinates (A: 2 chunks; W: 1 chunk)
    int a_mm0 = tid >> 2;            // 0..63
    int a_mm1 = 64 + (tid >> 2);     // 64..127
    int a_c8  = (tid & 3) * 8;       // bf16 col offset, 16B chunk
    int w_nn  = tid >> 2;
    int w_c8  = (tid & 3) * 8;

    auto load_tile = [&](int kt, int s) {
        int k0 = kt * GBK;
        cpasync16(&sAh[s][a_mm0][a_c8], &g_Ah[(size_t)(m0 + a_mm0) * F + k0 + a_c8]);
        cpasync16(&sAh[s][a_mm1][a_c8], &g_Ah[(size_t)(m0 + a_mm1) * F + k0 + a_c8]);
        cpasync16(&sAl[s][a_mm0][a_c8], &g_Al[(size_t)(m0 + a_mm0) * F + k0 + a_c8]);
        cpasync16(&sAl[s][a_mm1][a_c8], &g_Al[(size_t)(m0 + a_mm1) * F + k0 + a_c8]);
        cpasync16(&sWh[s][w_nn][w_c8], &g_Wh[(size_t)(n0 + w_nn) * F + k0 + w_c8]);
        cpasync16(&sWl[s][w_nn][w_c8], &g_Wl[(size_t)(n0 + w_nn) * F + k0 + w_c8]);
        asm volatile("cp.async.commit_group;");
    };

    float acc[2][4][4] = {};

    load_tile(0, 0);

    for (int kt = 0; kt < NKT; ++kt) {
        int s = kt & 1;
        asm volatile("cp.async.wait_group 0;");
        __syncthreads();
        if (kt + 1 < NKT) load_tile(kt + 1, s ^ 1);

        #pragma unroll
        for (int kk = 0; kk < GBK; kk += 16) {
            uint32_t ah[2][4], al[2][4];
            #pragma unroll
            for (int mi = 0; mi < 2; ++mi) {
                int rowa = wm * 32 + mi * 16 + (lane & 15);
                int cola = kk + (lane >> 4) * 8;
                ldmA4(ah[mi], (uint32_t)__cvta_generic_to_shared(&sAh[s][rowa][cola]));
                ldmA4(al[mi], (uint32_t)__cvta_generic_to_shared(&sAl[s][rowa][cola]));
            }
            uint32_t bh[4][2], bl[4][2];
            #pragma unroll
            for (int ni = 0; ni < 4; ++ni) {
                int rowb = wn * 32 + ni * 8 + (lane & 7);
                int colb = kk + ((lane >> 3) & 1) * 8;
                ldmB2(bh[ni], (uint32_t)__cvta_generic_to_shared(&sWh[s][rowb][colb]));
                ldmB2(bl[ni], (uint32_t)__cvta_generic_to_shared(&sWl[s][rowb][colb]));
            }
            #pragma unroll
            for (int mi = 0; mi < 2; ++mi)
                #pragma unroll
                for (int ni = 0; ni < 4; ++ni) {
                    mma16816(acc[mi][ni], ah[mi], bh[ni]);
                    mma16816(acc[mi][ni], ah[mi], bl[ni]);
                    mma16816(acc[mi][ni], al[mi], bh[ni]);
                }
        }
    }

    // Epilogue: bias + leaky_relu, float2 stores
    #pragma unroll
    for (int mi = 0; mi < 2; ++mi) {
        #pragma unroll
        for (int ni = 0; ni < 4; ++ni) {
            int m = m0 + wm * 32 + mi * 16 + (lane >> 2);
            int n = n0 + wn * 32 + ni * 8 + (lane & 3) * 2;
            float b0 = bias[n], b1 = bias[n + 1];
            float v0 = acc[mi][ni][0] + b0;
            float v1 = acc[mi][ni][1] + b1;
            float v2 = acc[mi][ni][2] + b0;
            float v3 = acc[mi][ni][3] + b1;
            float2 p0 = make_float2(v0 > 0.f ? v0 : 0.01f * v0,
                                    v1 > 0.f ? v1 : 0.01f * v1);
            float2 p1 = make_float2(v2 > 0.f ? v2 : 0.01f * v2,
                                    v3 > 0.f ? v3 : 0.01f * v3);
            *(float2*)&out[(size_t)m * F + n]       = p0;
            *(float2*)&out[(size_t)(m + 8) * F + n] = p1;
        }
    }
}

// ---------------------------------------------------------------------------
// Launch. Inputs (metadata order): D [N*N], X [N*F], A [N*N], W [F*F], b [F]
// ---------------------------------------------------------------------------
extern "C" void kernel_launch(void* const* d_in, const int* in_sizes, int n_in,
                              void* d_out, int out_size) {
    const float* D = (const float*)d_in[0];
    const float* X = (const float*)d_in[1];
    const float* A = (const float*)d_in[2];
    const float* W = (const float*)d_in[3];
    const float* b = (const float*)d_in[4];
    float* out = (float*)d_out;

    rd_kernel<<<N_NODES / 256, 256>>>(D);
    wsplit_kernel<<<F * F / 256, 256>>>(W);
    agg_kernel<<<N_NODES, 256>>>(A, X);

    dim3 grid(N_NODES / GBM, F / GBN);
    gemm_bf16_kernel<<<grid, 256>>>(b, out);
}

// round 5
// speedup vs baseline: 3.5000x; 1.1126x over previous
#include <cuda_runtime.h>
#include <cuda_bf16.h>
#include <cstdint>
#include <cstddef>

#define N_NODES 8192
#define F 256

// Scratch (allocation-free rule: device globals)
__device__ float g_rd[N_NODES];                          // rsqrt(deg)
__device__ __nv_bfloat16 g_Ah[(size_t)N_NODES * F];      // agg hi (bf16)
__device__ __nv_bfloat16 g_Al[(size_t)N_NODES * F];      // agg lo (bf16 residual)
__device__ __nv_bfloat16 g_Wh[(size_t)F * F];            // W hi
__device__ __nv_bfloat16 g_Wl[(size_t)F * F];            // W lo

// ---------------------------------------------------------------------------
// rd[j] = rsqrt(D[j,j])
// ---------------------------------------------------------------------------
__global__ void rd_kernel(const float* __restrict__ D) {
    int j = blockIdx.x * blockDim.x + threadIdx.x;
    if (j < N_NODES) g_rd[j] = rsqrtf(D[(size_t)j * (N_NODES + 1)]);
}

// ---------------------------------------------------------------------------
// Split W into bf16 hi + residual lo
// ---------------------------------------------------------------------------
__global__ void wsplit_kernel(const float* __restrict__ W) {
    int i = blockIdx.x * blockDim.x + threadIdx.x;
    float w = W[i];
    __nv_bfloat16 h = __float2bfloat16(w);
    g_Wh[i] = h;
    g_Wl[i] = __float2bfloat16(w - __bfloat162float(h));
}

// ---------------------------------------------------------------------------
// Sparse aggregation: one block (8 warps) per row; warp w autonomously owns
// column slice [w*1024, (w+1)*1024): scans it, compacts neighbors into a
// warp-private list, then gathers full 1KB X rows (lane owns 8 channels,
// 2x float4 per neighbor). No inter-warp barrier until the final reduce.
// ---------------------------------------------------------------------------
#define SLICE_CAP 160   // per-1024-col slice capacity (Binomial(1024,1/256), mean~4)

__global__ void agg_kernel(const float* __restrict__ A,
                           const float* __restrict__ X) {
    int row = blockIdx.x;
    int t = threadIdx.x;
    int warp = t >> 5;
    int lane = t & 31;

    __shared__ float s_part[8][F];           // per-warp partial sums (8 KB)
    __shared__ int s_idx[8][SLICE_CAP];      // per-warp neighbor lists
    __shared__ int s_cnt[8];
    __shared__ int s_minj;

    if (t < 8) s_cnt[t] = 0;
    if (t == 0) s_minj = N_NODES;
    __syncthreads();

    // ---- scan: warp slice = 1024 cols; lane loads 8 float4 (32 cols) ----
    const float4* Arow = (const float4*)(A + (size_t)row * N_NODES) + warp * 256;

    float4 v[8];
    #pragma unroll
    for (int c = 0; c < 8; ++c)
        v[c] = __ldcs(&Arow[c * 32 + lane]);

    int* my_idx = s_idx[warp];
    #pragma unroll
    for (int c = 0; c < 8; ++c) {
        int col0 = warp * 1024 + c * 128 + lane * 4;
        uint32_t nib = (v[c].x > 0.0f ? 1u : 0u) |
                       (v[c].y > 0.0f ? 2u : 0u) |
                       (v[c].z > 0.0f ? 4u : 0u) |
                       (v[c].w > 0.0f ? 8u : 0u);
        if (nib) {
            int n = __popc(nib);
            int off = atomicAdd(&s_cnt[warp], n);
            atomicMin(&s_minj, col0 + (__ffs(nib) - 1));
            while (nib) {
                int b = __ffs(nib) - 1;
                nib &= nib - 1;
                if (off < SLICE_CAP) my_idx[off] = col0 + b;
                ++off;
            }
        }
    }
    __syncwarp();

    // ---- gather: warp walks its own list; lane owns channels lane*8..+7 ----
    int cnt = s_cnt[warp];
    if (cnt > SLICE_CAP) cnt = SLICE_CAP;

    float4 acc0 = make_float4(0.f, 0.f, 0.f, 0.f);
    float4 acc1 = make_float4(0.f, 0.f, 0.f, 0.f);

    int i = 0;
    for (; i + 2 <= cnt; i += 2) {
        int j0 = my_idx[i], j1 = my_idx[i + 1];
        float r0 = g_rd[j0], r1 = g_rd[j1];
        const float4* x0 = (const float4*)(X + (size_t)j0 * F) + lane * 2;
        const float4* x1 = (const float4*)(X + (size_t)j1 * F) + lane * 2;
        float4 p0 = x0[0], p1 = x0[1], q0 = x1[0], q1 = x1[1];
        acc0.x += p0.x * r0; acc0.y += p0.y * r0; acc0.z += p0.z * r0; acc0.w += p0.w * r0;
        acc1.x += p1.x * r0; acc1.y += p1.y * r0; acc1.z += p1.z * r0; acc1.w += p1.w * r0;
        acc0.x += q0.x * r1; acc0.y += q0.y * r1; acc0.z += q0.z * r1; acc0.w += q0.w * r1;
        acc1.x += q1.x * r1; acc1.y += q1.y * r1; acc1.z += q1.z * r1; acc1.w += q1.w * r1;
    }
    if (i < cnt) {
        int j = my_idx[i];
        float r = g_rd[j];
        const float4* x = (const float4*)(X + (size_t)j * F) + lane * 2;
        float4 p0 = x[0], p1 = x[1];
        acc0.x += p0.x * r; acc0.y += p0.y * r; acc0.z += p0.z * r; acc0.w += p0.w * r;
        acc1.x += p1.x * r; acc1.y += p1.y * r; acc1.z += p1.z * r; acc1.w += p1.w * r;
    }

    ((float4*)s_part[warp])[lane * 2]     = acc0;
    ((float4*)s_part[warp])[lane * 2 + 1] = acc1;
    __syncthreads();

    // ---- reduce 8 partials, scale, bf16 hi/lo split ----
    float acc = 0.f;
    #pragma unroll
    for (int w = 0; w < 8; ++w) acc += s_part[w][t];
    acc *= g_rd[s_minj];

    __nv_bfloat16 h = __float2bfloat16(acc);
    float lo = acc - __bfloat162float(h);
    size_t oi = (size_t)row * F + t;
    g_Ah[oi] = h;
    g_Al[oi] = __float2bfloat16(lo);
}

// ---------------------------------------------------------------------------
// Tensor-core GEMM: out = leaky_relu(A @ W^T + b) via split bf16:
//   A@W^T ~= Ah@Wh^T + Ah@Wl^T + Al@Wh^T   (fp32 accumulate)
// cp.async double-buffered. Block tile 128x128, BK=32, 8 warps (2Mx4N),
// warp tile 64x32. Grid = 128 blocks (single wave, 1 block/SM).
// ---------------------------------------------------------------------------
#define GBM 128
#define GBN 128
#define GBK 32
#define SKP 40   // padded K extent in bf16 (80B rows)
#define NKT (F / GBK)

__device__ __forceinline__ void ldmA4(uint32_t* r, uint32_t addr) {
    asm volatile("ldmatrix.sync.aligned.m8n8.x4.shared.b16 {%0,%1,%2,%3}, [%4];"
        : "=r"(r[0]), "=r"(r[1]), "=r"(r[2]), "=r"(r[3]) : "r"(addr));
}
__device__ __forceinline__ void ldmB2(uint32_t* r, uint32_t addr) {
    asm volatile("ldmatrix.sync.aligned.m8n8.x2.shared.b16 {%0,%1}, [%2];"
        : "=r"(r[0]), "=r"(r[1]) : "r"(addr));
}
__device__ __forceinline__ void mma16816(float* d, const uint32_t* a, const uint32_t* b) {
    asm volatile("mma.sync.aligned.m16n8k16.row.col.f32.bf16.bf16.f32 "
        "{%0,%1,%2,%3}, {%4,%5,%6,%7}, {%8,%9}, {%0,%1,%2,%3};"
        : "+f"(d[0]), "+f"(d[1]), "+f"(d[2]), "+f"(d[3])
        : "r"(a[0]), "r"(a[1]), "r"(a[2]), "r"(a[3]), "r"(b[0]), "r"(b[1]));
}
__device__ __forceinline__ void cpasync16(void* smem_dst, const void* gsrc) {
    uint32_t d = (uint32_t)__cvta_generic_to_shared(smem_dst);
    asm volatile("cp.async.cg.shared.global [%0], [%1], 16;" :: "r"(d), "l"(gsrc));
}

__global__ __launch_bounds__(256, 1)
void gemm_bf16_kernel(const float* __restrict__ bias,
                      float* __restrict__ out) {
    __shared__ __align__(16) __nv_bfloat16 sAh[2][GBM][SKP];
    __shared__ __align__(16) __nv_bfloat16 sAl[2][GBM][SKP];
    __shared__ __align__(16) __nv_bfloat16 sWh[2][GBN][SKP];
    __shared__ __align__(16) __nv_bfloat16 sWl[2][GBN][SKP];

    int tid = threadIdx.x;
    int warp = tid >> 5;
    int lane = tid & 31;
    int m0 = blockIdx.x * GBM;
    int n0 = blockIdx.y * GBN;
    int wm = warp & 1;    // 0..1 -> m offset wm*64
    int wn = warp >> 1;   // 0..3 -> n offset wn*32

    auto load_tile = [&](int kt, int s) {
        int k0 = kt * GBK;
        #pragma unroll
        for (int r = 0; r < 2; ++r) {
            int idx = r * 256 + tid;     // 0..511
            int mm  = idx >> 2;          // 0..127
            int c8  = (idx & 3) * 8;
            size_t gi = (size_t)(m0 + mm) * F + k0 + c8;
            cpasync16(&sAh[s][mm][c8], &g_Ah[gi]);
            cpasync16(&sAl[s][mm][c8], &g_Al[gi]);
            size_t wi = (size_t)(n0 + mm) * F + k0 + c8;
            cpasync16(&sWh[s][mm][c8], &g_Wh[wi]);
            cpasync16(&sWl[s][mm][c8], &g_Wl[wi]);
        }
        asm volatile("cp.async.commit_group;");
    };

    float acc[4][4][4] = {};

    load_tile(0, 0);

    for (int kt = 0; kt < NKT; ++kt) {
        int s = kt & 1;
        asm volatile("cp.async.wait_group 0;");
        __syncthreads();
        if (kt + 1 < NKT) load_tile(kt + 1, s ^ 1);

        #pragma unroll
        for (int kk = 0; kk < GBK; kk += 16) {
            uint32_t ah[4][4], al[4][4];
            #pragma unroll
            for (int mi = 0; mi < 4; ++mi) {
                int rowa = wm * 64 + mi * 16 + (lane & 15);
                int cola = kk + (lane >> 4) * 8;
                ldmA4(ah[mi], (uint32_t)__cvta_generic_to_shared(&sAh[s][rowa][cola]));
                ldmA4(al[mi], (uint32_t)__cvta_generic_to_shared(&sAl[s][rowa][cola]));
            }
            uint32_t bh[4][2], bl[4][2];
            #pragma unroll
            for (int ni = 0; ni < 4; ++ni) {
                int rowb = wn * 32 + ni * 8 + (lane & 7);
                int colb = kk + ((lane >> 3) & 1) * 8;
                ldmB2(bh[ni], (uint32_t)__cvta_generic_to_shared(&sWh[s][rowb][colb]));
                ldmB2(bl[ni], (uint32_t)__cvta_generic_to_shared(&sWl[s][rowb][colb]));
            }
            #pragma unroll
            for (int mi = 0; mi < 4; ++mi)
                #pragma unroll
                for (int ni = 0; ni < 4; ++ni) {
                    mma16816(acc[mi][ni], ah[mi], bh[ni]);
                    mma16816(acc[mi][ni], ah[mi], bl[ni]);
                    mma16816(acc[mi][ni], al[mi], bh[ni]);
                }
        }
    }

    // Epilogue: bias + leaky_relu, float2 stores
    #pragma unroll
    for (int mi = 0; mi < 4; ++mi) {
        #pragma unroll
        for (int ni = 0; ni < 4; ++ni) {
            int m = m0 + wm * 64 + mi * 16 + (lane >> 2);
            int n = n0 + wn * 32 + ni * 8 + (lane & 3) * 2;
            float b0 = bias[n], b1 = bias[n + 1];
            float v0 = acc[mi][ni][0] + b0;
            float v1 = acc[mi][ni][1] + b1;
            float v2 = acc[mi][ni][2] + b0;
            float v3 = acc[mi][ni][3] + b1;
            float2 p0 = make_float2(v0 > 0.f ? v0 : 0.01f * v0,
                                    v1 > 0.f ? v1 : 0.01f * v1);
            float2 p1 = make_float2(v2 > 0.f ? v2 : 0.01f * v2,
                                    v3 > 0.f ? v3 : 0.01f * v3);
            *(float2*)&out[(size_t)m * F + n]       = p0;
            *(float2*)&out[(size_t)(m + 8) * F + n] = p1;
        }
    }
}

// ---------------------------------------------------------------------------
// Launch. Inputs (metadata order): D [N*N], X [N*F], A [N*N], W [F*F], b [F]
// ---------------------------------------------------------------------------
extern "C" void kernel_launch(void* const* d_in, const int* in_sizes, int n_in,
                              void* d_out, int out_size) {
    const float* D = (const float*)d_in[0];
    const float* X = (const float*)d_in[1];
    const float* A = (const float*)d_in[2];
    const float* W = (const float*)d_in[3];
    const float* b = (const float*)d_in[4];
    float* out = (float*)d_out;

    rd_kernel<<<N_NODES / 256, 256>>>(D);
    wsplit_kernel<<<F * F / 256, 256>>>(W);
    agg_kernel<<<N_NODES, 256>>>(A, X);

    dim3 grid(N_NODES / GBM, F / GBN);
    gemm_bf16_kernel<<<grid, 256>>>(b, out);
}